// round 8
// baseline (speedup 1.0000x reference)
#include <cuda_runtime.h>
#include <cstdint>

#define FM 0xffffffffu
#define NW 32
#define INFV 1000000000.0f
#define KMASK 0xFFFFFFE0u   // key: high 27 bits value, low 5 bits lane

struct Feat {
    float cx, cy, area, sr, ar, bx, by, prob;
};

__device__ __forceinline__ Feat wall_features(const float* __restrict__ q) {
    float sx = q[0], sy = q[1], ex = q[2], ey = q[3], w = q[4], prob = q[5];
    float dx = ex - sx, dy = ey - sy;
    float len = sqrtf(dx * dx + dy * dy);
    float cx = (sx + ex) * 0.5f, cy = (sy + ey) * 0.5f;
    float area = len * w;
    float smaller = fminf(w, len), bigger = fmaxf(w, len);
    float sr = (bigger > 0.0f) ? (smaller / bigger) : 0.0f;
    float px, py;
    if (len > 0.0f) {
        float s = w * 0.5f / len;
        px = dy * s;
        py = -dx * s;
    } else {
        px = 0.0f;
        py = 0.0f;
    }
    float right = fmaxf(fmaxf(sx + px, sx - px), fmaxf(ex + px, ex - px));
    float top   = fmaxf(fmaxf(sy + py, sy - py), fmaxf(ey + py, ey - py));
    float bbw = fabsf((right - cx) * 2.0f);
    float bbh = fabsf((top  - cy) * 2.0f);
    float bba = bbw * bbh;
    float ar = (bba > 0.001f) ? (area / bba) : 1.0f;
    Feat f;
    f.cx = cx; f.cy = cy; f.area = area; f.sr = sr; f.ar = ar;
    f.bx = bbw; f.by = bbh; f.prob = prob;
    return f;
}

// One warp per batch; columns (pred walls) <-> lanes.
// JV: column reduction + kick-free free-row pass + SAP with column-staged
// reduced-cost matrix M[j][l] = C[row4col[j]][l] - u[row4col[j]], removing
// the row-indirection shfl from the SAP critical chain.
__global__ void __launch_bounds__(32)
floorplanet_kernel(const float* __restrict__ params_true,
                   const float* __restrict__ params_pred,
                   float* __restrict__ out) {
    __shared__ float C[NW * NW];
    __shared__ float M[NW * NW];
    __shared__ float u_sh[NW];
    __shared__ float du_sh[NW];
    __shared__ int r_sh[NW];
    __shared__ int c4r_sh[NW];

    const int b = blockIdx.x;
    const int lane = threadIdx.x;

    Feat ft = wall_features(params_true + (size_t)b * NW * 6 + lane * 6);
    Feat fp = wall_features(params_pred + (size_t)b * NW * 6 + lane * 6);

    // Fill C[i][lane]; track column min on the fly.
    float cm = INFV;
    int am = 0;
#pragma unroll 4
    for (int i = 0; i < NW; i++) {
        float icx   = __shfl_sync(FM, ft.cx,   i);
        float icy   = __shfl_sync(FM, ft.cy,   i);
        float iarea = __shfl_sync(FM, ft.area, i);
        float isr   = __shfl_sync(FM, ft.sr,   i);
        float iar   = __shfl_sync(FM, ft.ar,   i);
        float ibx   = __shfl_sync(FM, ft.bx,   i);
        float iby   = __shfl_sync(FM, ft.by,   i);
        float iprob = __shfl_sync(FM, ft.prob, i);

        float dcx = icx - fp.cx, dcy = icy - fp.cy;
        float center_d = dcx * dcx + dcy * dcy;
        float da = iarea - fp.area;
        float ds = isr   - fp.sr;
        float dr = iar   - fp.ar;
        float dh = ibx   - fp.bx;
        float dv = iby   - fp.by;
        float dp = iprob - fp.prob;

        float param_d = da * da + center_d + dr * dr + dh * dh + dv * dv + ds * ds;
        float cost = 10.0f * (dp * dp) + param_d * iprob;
        C[i * NW + lane] = cost;
        if (cost < cm) { cm = cost; am = i; }
    }
    __syncwarp();

    // ---- Phase 1: column reduction. v[j]=colmin, greedily match argmin rows.
    float v = cm, u = 0.0f;
    unsigned grp = __match_any_sync(FM, am);
    bool winner = ((__ffs(grp) - 1) == lane);
    int row4col = winner ? am : -1;
    c4r_sh[lane] = -1;
    __syncwarp();
    if (winner) c4r_sh[am] = lane;
    __syncwarp();
    int col4row = c4r_sh[lane];
    unsigned freerows = __ballot_sync(FM, col4row < 0);

    // ---- Phase 2': kick-free free-row pass. Each free row takes its argmin
    // column iff unmatched; else keeps feasible dual u[i] = min reduced cost
    // (rounded down -> reduced costs stay >= 0) and stays free for SAP.
    unsigned rem = freerows;
    while (rem) {
        const int i = __ffs(rem) - 1;
        rem &= rem - 1;
        float d = fmaxf(C[i * NW + lane] - v, 0.0f);
        unsigned k = (__float_as_uint(d) & KMASK) | (unsigned)lane;
        unsigned m = __reduce_min_sync(FM, k);
        int j = m & 31;
        int r = __shfl_sync(FM, row4col, j);
        float umin = __uint_as_float(m & KMASK);
        if (lane == i) u = umin;
        if (r < 0) {
            if (lane == j) row4col = i;
            if (lane == i) col4row = j;
            freerows &= ~(1u << i);
        }
    }

    // ---- Phase 3: SAP with biased slacks (slackb = slack + 1 > 0) and
    // column-staged matrix M[j][l] = C[r_j][l] - u[r_j].
    unsigned freecols = __ballot_sync(FM, row4col < 0);
    if (freerows) {
        u_sh[lane] = u;
        r_sh[lane] = row4col;
        __syncwarp();
        for (int j = 0; j < NW; j++) {
            int r = r_sh[j];
            if (r >= 0) M[j * NW + lane] = C[r * NW + lane] - u_sh[r];
        }
        __syncwarp();
    }

    while (freerows) {
        const int i0 = __ffs(freerows) - 1;
        freerows &= freerows - 1;

        float ui = __shfl_sync(FM, u, i0);
        unsigned SC = 0u;
        unsigned mkey = 0xFFFFFFFFu;
        unsigned laneor = (unsigned)lane;       // ~0 once lane enters SC
        float spcb = INFV;
        int path = -1;
        float minValb = 1.0f;
        int i = i0;                             // row producing current slackb
        float slackb = (C[i0 * NW + lane] - ui - v) + 1.0f;   // >= 1
        int sink;

        for (;;) {
            unsigned skey = (__float_as_uint(slackb) & KMASK) | laneor;
            if (skey < mkey) {                  // off-chain bookkeeping
                spcb = __uint_as_float(skey & KMASK);
                path = i;
            }
            mkey = umin(mkey, skey);
            unsigned om = __reduce_min_sync(FM, mkey);
            int j = om & 31;
            minValb = __uint_as_float(om & KMASK);
            SC |= 1u << j;
            if (lane == j) { laneor = 0xFFFFFFFFu; mkey = 0xFFFFFFFFu; }
            if ((freecols >> j) & 1u) { sink = j; break; }
            i = r_sh[j];                        // broadcast LDS, off-chain
            slackb = M[j * NW + lane] + (minValb - v);  // on-chain LDS + FADD
        }

        // Dual updates. SC lanes (except sink) scatter to their matched row.
        float add = minValb - spcb;
        du_sh[lane] = 0.0f;
        __syncwarp();
        if (((SC >> lane) & 1u) && lane != sink) du_sh[row4col] = add;
        __syncwarp();
        u += (lane == i0) ? (minValb - 1.0f) : du_sh[lane];
        if ((SC >> lane) & 1u) v -= add;

        // Augment along alternating path.
        int j = sink;
        bool done = false;
        while (!done) {
            int pi = __shfl_sync(FM, path, j);
            if (lane == j) row4col = pi;
            int jn = __shfl_sync(FM, col4row, pi);
            if (lane == pi) col4row = j;
            done = (pi == i0);
            j = jn;
        }

        // Refresh M rows for SC columns (their rows/duals changed); sink is
        // now matched.
        freecols &= ~(1u << sink);
        u_sh[lane] = u;
        r_sh[lane] = row4col;
        __syncwarp();
        unsigned scit = SC;
        while (scit) {
            int j2 = __ffs(scit) - 1;
            scit &= scit - 1;
            int r = r_sh[j2];
            M[j2 * NW + lane] = C[r * NW + lane] - u_sh[r];
        }
        __syncwarp();
    }

    // loss = sum_i C[i][col4row[i]]
    float c = C[lane * NW + (col4row & 31)];
#pragma unroll
    for (int off = 16; off > 0; off >>= 1)
        c += __shfl_xor_sync(FM, c, off);
    if (lane == 0) out[b] = c;
}

extern "C" void kernel_launch(void* const* d_in, const int* in_sizes, int n_in,
                              void* d_out, int out_size) {
    const float* params_true = (const float*)d_in[0];
    const float* params_pred = (const float*)d_in[1];
    float* out = (float*)d_out;
    (void)in_sizes; (void)n_in; (void)out_size;
    floorplanet_kernel<<<2048, 32>>>(params_true, params_pred, out);
}

// round 9
// speedup vs baseline: 1.3906x; 1.3906x over previous
#include <cuda_runtime.h>
#include <cstdint>

#define FM 0xffffffffu
#define NW 32
#define INFV 1000000000.0f
#define KMASK 0xFFFFFFE0u   // key: high 27 bits value, low 5 bits lane

struct Feat {
    float cx, cy, area, sr, ar, bx, by, prob;
};

__device__ __forceinline__ Feat wall_features(const float* __restrict__ q) {
    float sx = q[0], sy = q[1], ex = q[2], ey = q[3], w = q[4], prob = q[5];
    float dx = ex - sx, dy = ey - sy;
    float len = sqrtf(dx * dx + dy * dy);
    float cx = (sx + ex) * 0.5f, cy = (sy + ey) * 0.5f;
    float area = len * w;
    float smaller = fminf(w, len), bigger = fmaxf(w, len);
    float sr = (bigger > 0.0f) ? (smaller / bigger) : 0.0f;
    float px, py;
    if (len > 0.0f) {
        float s = w * 0.5f / len;
        px = dy * s;
        py = -dx * s;
    } else {
        px = 0.0f;
        py = 0.0f;
    }
    float right = fmaxf(fmaxf(sx + px, sx - px), fmaxf(ex + px, ex - px));
    float top   = fmaxf(fmaxf(sy + py, sy - py), fmaxf(ey + py, ey - py));
    float bbw = fabsf((right - cx) * 2.0f);
    float bbh = fabsf((top  - cy) * 2.0f);
    float bba = bbw * bbh;
    float ar = (bba > 0.001f) ? (area / bba) : 1.0f;
    Feat f;
    f.cx = cx; f.cy = cy; f.area = area; f.sr = sr; f.ar = ar;
    f.bx = bbw; f.by = bbh; f.prob = prob;
    return f;
}

// One warp per batch; columns (pred walls) <-> lanes.
// JV: column reduction + kick-free free-row pass + SAP.
// SAP stages M[j][l] = C[row4col[j]][l] (no duals folded -> no refresh except
// during augmentation), so the slack LDS address depends only on the selected
// column j: the row4col shfl leaves the critical chain.
__global__ void __launch_bounds__(32)
floorplanet_kernel(const float* __restrict__ params_true,
                   const float* __restrict__ params_pred,
                   float* __restrict__ out) {
    __shared__ float C[NW * NW];
    __shared__ float M[NW * NW];
    __shared__ int c4r_sh[NW];
    __shared__ int r_sh[NW];

    const int b = blockIdx.x;
    const int lane = threadIdx.x;

    Feat ft = wall_features(params_true + (size_t)b * NW * 6 + lane * 6);
    Feat fp = wall_features(params_pred + (size_t)b * NW * 6 + lane * 6);

    // Fill C[i][lane]; track column min on the fly.
    float cm = INFV;
    int am = 0;
#pragma unroll 4
    for (int i = 0; i < NW; i++) {
        float icx   = __shfl_sync(FM, ft.cx,   i);
        float icy   = __shfl_sync(FM, ft.cy,   i);
        float iarea = __shfl_sync(FM, ft.area, i);
        float isr   = __shfl_sync(FM, ft.sr,   i);
        float iar   = __shfl_sync(FM, ft.ar,   i);
        float ibx   = __shfl_sync(FM, ft.bx,   i);
        float iby   = __shfl_sync(FM, ft.by,   i);
        float iprob = __shfl_sync(FM, ft.prob, i);

        float dcx = icx - fp.cx, dcy = icy - fp.cy;
        float center_d = dcx * dcx + dcy * dcy;
        float da = iarea - fp.area;
        float ds = isr   - fp.sr;
        float dr = iar   - fp.ar;
        float dh = ibx   - fp.bx;
        float dv = iby   - fp.by;
        float dp = iprob - fp.prob;

        float param_d = da * da + center_d + dr * dr + dh * dh + dv * dv + ds * ds;
        float cost = 10.0f * (dp * dp) + param_d * iprob;
        C[i * NW + lane] = cost;
        if (cost < cm) { cm = cost; am = i; }
    }
    __syncwarp();

    // ---- Phase 1: column reduction. v[j]=colmin, greedily match argmin rows.
    float v = cm, u = 0.0f;
    unsigned grp = __match_any_sync(FM, am);
    bool winner = ((__ffs(grp) - 1) == lane);
    int row4col = winner ? am : -1;
    c4r_sh[lane] = -1;
    __syncwarp();
    if (winner) c4r_sh[am] = lane;
    __syncwarp();
    int col4row = c4r_sh[lane];
    unsigned freerows = __ballot_sync(FM, col4row < 0);

    // ---- Phase 2': kick-free free-row pass. Each free row takes its argmin
    // column iff unmatched; else keeps feasible dual u[i] = min reduced cost
    // (rounded down -> reduced costs stay >= 0) and stays free for SAP.
    unsigned rem = freerows;
    while (rem) {
        const int i = __ffs(rem) - 1;
        rem &= rem - 1;
        float d = fmaxf(C[i * NW + lane] - v, 0.0f);
        unsigned k = (__float_as_uint(d) & KMASK) | (unsigned)lane;
        unsigned m = __reduce_min_sync(FM, k);
        int j = m & 31;
        int r = __shfl_sync(FM, row4col, j);
        float umin = __uint_as_float(m & KMASK);
        if (lane == i) u = umin;
        if (r < 0) {
            if (lane == j) row4col = i;
            if (lane == i) col4row = j;
            freerows &= ~(1u << i);
        }
    }

    // ---- Phase 3: SAP, biased slacks (slackb = slack + 1 > 0).
    unsigned freecols = __ballot_sync(FM, row4col < 0);
    if (freerows) {
        // Stage M[j][l] = C[row4col[j]][l] for matched columns (once).
        r_sh[lane] = row4col;
        __syncwarp();
#pragma unroll 1
        for (int j = 0; j < NW; j++) {
            int r = r_sh[j];
            if (r >= 0) M[j * NW + lane] = C[r * NW + lane];
        }
    }

    while (freerows) {
        const int i0 = __ffs(freerows) - 1;
        freerows &= freerows - 1;

        float ur = __shfl_sync(FM, u, row4col & 31);  // u[row4col[lane]]
        float ui = __shfl_sync(FM, u, i0);
        unsigned SR = 1u << i0, SC = 0u;
        unsigned mkey = 0xFFFFFFFFu;
        unsigned laneor = (unsigned)lane;   // ~0 once lane enters SC
        float spcb = INFV;
        int path = -1;
        float minValb = 1.0f;
        int i = i0;                         // row producing current slackb
        float slackb = (C[i0 * NW + lane] - ui - v) + 1.0f;   // >= 1
        int sink;

        for (;;) {
            unsigned skey = (__float_as_uint(slackb) & KMASK) | laneor;
            if (skey < mkey) {              // off-chain bookkeeping
                spcb = __uint_as_float(skey & KMASK);
                path = i;
            }
            mkey = umin(mkey, skey);
            unsigned om = __reduce_min_sync(FM, mkey);
            int j = om & 31;
            minValb = __uint_as_float(om & KMASK);
            SC |= 1u << j;
            if (lane == j) { laneor = 0xFFFFFFFFu; mkey = 0xFFFFFFFFu; }
            if ((freecols >> j) & 1u) { sink = j; break; }
            int r     = __shfl_sync(FM, row4col, j);  // off-chain (SR/path)
            float urj = __shfl_sync(FM, ur, j);       // overlaps the M LDS
            SR |= 1u << r;
            i = r;
            slackb = M[j * NW + lane] - ((urj - minValb) + v);
        }

        // Dual updates: bias cancels in differences; only u[i0] needs -1.
        float spcb_c4r = __shfl_sync(FM, spcb, col4row & 31);
        if ((SR >> lane) & 1u)
            u += (lane == i0) ? (minValb - 1.0f) : (minValb - spcb_c4r);
        if ((SC >> lane) & 1u) v -= minValb - spcb;

        // Augment along alternating path; refresh M for re-matched columns.
        int j = sink;
        bool done = false;
        while (!done) {
            int pi = __shfl_sync(FM, path, j);
            if (lane == j) row4col = pi;
            M[j * NW + lane] = C[pi * NW + lane];     // same-lane slot: no sync
            int jn = __shfl_sync(FM, col4row, pi);
            if (lane == pi) col4row = j;
            done = (pi == i0);
            j = jn;
        }
        freecols &= ~(1u << sink);
    }

    // loss = sum_i C[i][col4row[i]]
    float c = C[lane * NW + (col4row & 31)];
#pragma unroll
    for (int off = 16; off > 0; off >>= 1)
        c += __shfl_xor_sync(FM, c, off);
    if (lane == 0) out[b] = c;
}

extern "C" void kernel_launch(void* const* d_in, const int* in_sizes, int n_in,
                              void* d_out, int out_size) {
    const float* params_true = (const float*)d_in[0];
    const float* params_pred = (const float*)d_in[1];
    float* out = (float*)d_out;
    (void)in_sizes; (void)n_in; (void)out_size;
    floorplanet_kernel<<<2048, 32>>>(params_true, params_pred, out);
}